// round 2
// baseline (speedup 1.0000x reference)
#include <cuda_runtime.h>
#include <cstdint>

#define NN 100000
#define NE 1600000
#define H1 128
#define H2 64

// ---------------- scratch (static device globals; no allocation) -------------
__device__ int   g_deg[NN];
__device__ int   g_rowptr[NN + 1];
__device__ int   g_fill[NN];
__device__ int   g_stmp[NN];
__device__ int   g_bsum[128];
__device__ int   g_ci[NE];
__device__ float g_cw[NE];
__device__ float g_h1[(size_t)NN * H1];
__device__ float g_h2[(size_t)NN * H1];
__device__ float g_z1[(size_t)NN * H2];

// ---------------- CSR build --------------------------------------------------
__global__ void k_zero_deg() {
    int i = blockIdx.x * blockDim.x + threadIdx.x;
    if (i < NN) g_deg[i] = 0;
}

__global__ void k_hist(const int* __restrict__ ei) {
    int e = blockIdx.x * blockDim.x + threadIdx.x;
    if (e < NE) atomicAdd(&g_deg[ei[e]], 1);   // ei[0..NE) = dst
}

// block-level inclusive scan of degrees (1024 per block)
__global__ void k_scan1() {
    __shared__ int s[1024];
    int tid = threadIdx.x;
    int i = blockIdx.x * 1024 + tid;
    int v = (i < NN) ? g_deg[i] : 0;
    s[tid] = v;
    __syncthreads();
#pragma unroll
    for (int off = 1; off < 1024; off <<= 1) {
        int t = (tid >= off) ? s[tid - off] : 0;
        __syncthreads();
        s[tid] += t;
        __syncthreads();
    }
    if (i < NN) g_stmp[i] = s[tid];
    if (tid == 1023) g_bsum[blockIdx.x] = s[1023];
}

__global__ void k_scan2(int nb) {
    if (threadIdx.x == 0) {
        int acc = 0;
        for (int b = 0; b < nb; b++) { int t = g_bsum[b]; g_bsum[b] = acc; acc += t; }
    }
}

__global__ void k_scan3() {
    int i = blockIdx.x * blockDim.x + threadIdx.x;
    if (i < NN) {
        int incl = g_stmp[i] + g_bsum[i >> 10];
        g_rowptr[i + 1] = incl;
        g_fill[i] = incl - g_deg[i];
        if (i == 0) g_rowptr[0] = 0;
    }
}

__global__ void k_fill(const int* __restrict__ ei, const float* __restrict__ ew) {
    int e = blockIdx.x * blockDim.x + threadIdx.x;
    if (e < NE) {
        int d = ei[e];          // dst
        int s = ei[NE + e];     // src
        int p = atomicAdd(&g_fill[d], 1);
        g_ci[p] = s;
        g_cw[p] = ew[e];
    }
}

// ---------------- SGEMM (C[m,n] = sum_k A[m,k]*W[n,k] + bias[n]) -------------
template <int BM, int BN, int BK, int TM, int TN>
__global__ void k_sgemm_bias(const float* __restrict__ A, const float* __restrict__ W,
                             const float* __restrict__ bias, float* __restrict__ C,
                             int M, int N, int K) {
    constexpr int THREADS = (BM / TM) * (BN / TN);
    __shared__ float As[BK][BM];
    __shared__ float Bs[BK][BN];
    const int tid = threadIdx.x;
    const int tx = tid % (BN / TN);
    const int ty = tid / (BN / TN);
    const int m0 = blockIdx.x * BM;

    float acc[TM][TN];
#pragma unroll
    for (int i = 0; i < TM; i++)
#pragma unroll
        for (int j = 0; j < TN; j++) acc[i][j] = 0.f;

    for (int k0 = 0; k0 < K; k0 += BK) {
#pragma unroll
        for (int t = tid; t < BM * BK / 4; t += THREADS) {
            int r = t / (BK / 4), c = t % (BK / 4);
            float4 v = make_float4(0.f, 0.f, 0.f, 0.f);
            int m = m0 + r;
            if (m < M) v = *reinterpret_cast<const float4*>(A + (size_t)m * K + k0 + c * 4);
            As[c * 4 + 0][r] = v.x; As[c * 4 + 1][r] = v.y;
            As[c * 4 + 2][r] = v.z; As[c * 4 + 3][r] = v.w;
        }
#pragma unroll
        for (int t = tid; t < BN * BK / 4; t += THREADS) {
            int r = t / (BK / 4), c = t % (BK / 4);
            float4 v = *reinterpret_cast<const float4*>(W + (size_t)r * K + k0 + c * 4);
            Bs[c * 4 + 0][r] = v.x; Bs[c * 4 + 1][r] = v.y;
            Bs[c * 4 + 2][r] = v.z; Bs[c * 4 + 3][r] = v.w;
        }
        __syncthreads();
#pragma unroll
        for (int k = 0; k < BK; k++) {
            float a[TM], b[TN];
#pragma unroll
            for (int i = 0; i < TM; i += 4) {
                float4 v = *reinterpret_cast<const float4*>(&As[k][ty * TM + i]);
                a[i] = v.x; a[i + 1] = v.y; a[i + 2] = v.z; a[i + 3] = v.w;
            }
#pragma unroll
            for (int j = 0; j < TN; j += 4) {
                float4 v = *reinterpret_cast<const float4*>(&Bs[k][tx * TN + j]);
                b[j] = v.x; b[j + 1] = v.y; b[j + 2] = v.z; b[j + 3] = v.w;
            }
#pragma unroll
            for (int i = 0; i < TM; i++)
#pragma unroll
                for (int j = 0; j < TN; j++) acc[i][j] = fmaf(a[i], b[j], acc[i][j]);
        }
        __syncthreads();
    }
#pragma unroll
    for (int i = 0; i < TM; i++) {
        int m = m0 + ty * TM + i;
        if (m < M) {
#pragma unroll
            for (int j = 0; j < TN; j += 4) {
                int n = tx * TN + j;
                float4 v;
                v.x = acc[i][j + 0] + bias[n + 0];
                v.y = acc[i][j + 1] + bias[n + 1];
                v.z = acc[i][j + 2] + bias[n + 2];
                v.w = acc[i][j + 3] + bias[n + 3];
                *reinterpret_cast<float4*>(C + (size_t)m * N + n) = v;
            }
        }
    }
}

// ---------------- SpMM gather: one warp per dst row ---------------------------
template <bool RELU>
__global__ void k_spmm128(const float* __restrict__ Hsrc, float* __restrict__ O) {
    int w = (blockIdx.x * blockDim.x + threadIdx.x) >> 5;
    if (w >= NN) return;
    int lane = threadIdx.x & 31;
    int beg = g_rowptr[w], end = g_rowptr[w + 1];
    float4 acc = make_float4(0.f, 0.f, 0.f, 0.f);
    for (int e = beg; e < end; e += 32) {
        int idx = e + lane;
        int s = 0; float wt = 0.f;
        if (idx < end) { s = g_ci[idx]; wt = g_cw[idx]; }
        int cnt = min(32, end - e);
        for (int j = 0; j < cnt; j++) {
            int sj = __shfl_sync(0xffffffffu, s, j);
            float wj = __shfl_sync(0xffffffffu, wt, j);
            float4 v = *reinterpret_cast<const float4*>(Hsrc + (size_t)sj * H1 + lane * 4);
            acc.x = fmaf(wj, v.x, acc.x);
            acc.y = fmaf(wj, v.y, acc.y);
            acc.z = fmaf(wj, v.z, acc.z);
            acc.w = fmaf(wj, v.w, acc.w);
        }
    }
    if (RELU) {
        acc.x = fmaxf(acc.x, 0.f); acc.y = fmaxf(acc.y, 0.f);
        acc.z = fmaxf(acc.z, 0.f); acc.w = fmaxf(acc.w, 0.f);
    }
    *reinterpret_cast<float4*>(O + (size_t)w * H1 + lane * 4) = acc;
}

__global__ void k_spmm64_norm(const float* __restrict__ Z, float* __restrict__ O) {
    int w = (blockIdx.x * blockDim.x + threadIdx.x) >> 5;
    if (w >= NN) return;
    int lane = threadIdx.x & 31;
    int beg = g_rowptr[w], end = g_rowptr[w + 1];
    float2 acc = make_float2(0.f, 0.f);
    for (int e = beg; e < end; e += 32) {
        int idx = e + lane;
        int s = 0; float wt = 0.f;
        if (idx < end) { s = g_ci[idx]; wt = g_cw[idx]; }
        int cnt = min(32, end - e);
        for (int j = 0; j < cnt; j++) {
            int sj = __shfl_sync(0xffffffffu, s, j);
            float wj = __shfl_sync(0xffffffffu, wt, j);
            float2 v = *reinterpret_cast<const float2*>(Z + (size_t)sj * H2 + lane * 2);
            acc.x = fmaf(wj, v.x, acc.x);
            acc.y = fmaf(wj, v.y, acc.y);
        }
    }
    float ss = acc.x * acc.x + acc.y * acc.y;
#pragma unroll
    for (int off = 16; off > 0; off >>= 1) ss += __shfl_xor_sync(0xffffffffu, ss, off);
    float inv = 1.f / fmaxf(sqrtf(ss), 1e-12f);
    float2 o = make_float2(acc.x * inv, acc.y * inv);
    *reinterpret_cast<float2*>(O + (size_t)w * H2 + lane * 2) = o;
}

// ---------------- launch ------------------------------------------------------
extern "C" void kernel_launch(void* const* d_in, const int* in_sizes, int n_in,
                              void* d_out, int out_size) {
    const float* x  = (const float*)d_in[0];
    const int*   ei = (const int*)d_in[1];
    const float* ew = (const float*)d_in[2];
    const float* W1 = (const float*)d_in[3];
    const float* b1 = (const float*)d_in[4];
    const float* W2 = (const float*)d_in[5];
    const float* b2 = (const float*)d_in[6];
    float* out = (float*)d_out;

    void *p_h1, *p_h2, *p_z1;
    cudaGetSymbolAddress(&p_h1, g_h1);
    cudaGetSymbolAddress(&p_h2, g_h2);
    cudaGetSymbolAddress(&p_z1, g_z1);
    float* h1 = (float*)p_h1;
    float* h2 = (float*)p_h2;
    float* z1 = (float*)p_z1;

    const int NB = (NN + 1023) / 1024;  // 98

    // CSR build (by dst)
    k_zero_deg<<<(NN + 255) / 256, 256>>>();
    k_hist<<<(NE + 255) / 256, 256>>>(ei);
    k_scan1<<<NB, 1024>>>();
    k_scan2<<<1, 32>>>(NB);
    k_scan3<<<(NN + 255) / 256, 256>>>();
    k_fill<<<(NE + 255) / 256, 256>>>(ei, ew);

    // Layer 1: h1 = x @ W1^T + b1   [100000,256]x[128,256] -> [100000,128]
    k_sgemm_bias<64, 128, 16, 8, 8><<<(NN + 63) / 64, 128>>>(x, W1, b1, h1, NN, H1, 256);
    // h2 = relu(spmm(h1))
    k_spmm128<true><<<(NN * 32 + 255) / 256, 256>>>(h1, h2);

    // Layer 2: z1 = h2 @ W2^T + b2   [100000,128]x[64,128] -> [100000,64]
    k_sgemm_bias<128, 64, 16, 8, 8><<<(NN + 127) / 128, 128>>>(h2, W2, b2, z1, NN, H2, 128);
    // out = normalize(spmm(z1))
    k_spmm64_norm<<<(NN * 32 + 255) / 256, 256>>>(z1, out);
}

// round 3
// speedup vs baseline: 1.6924x; 1.6924x over previous
#include <cuda_runtime.h>
#include <cstdint>

#define NN 100000
#define NE 1600000
#define H1 128
#define H2 64

// ---------------- scratch (static device globals; no allocation) -------------
__device__ int   g_deg[NN];
__device__ int   g_rowptr[NN + 1];
__device__ int   g_fill[NN];
__device__ int   g_stmp[NN];
__device__ int   g_bsum[128];
__device__ int   g_ci[NE];
__device__ float g_cw[NE];
__device__ float g_h1[(size_t)NN * H1];
__device__ float g_h2[(size_t)NN * H1];
__device__ float g_z1[(size_t)NN * H2];

// ---------------- CSR build --------------------------------------------------
__global__ void k_zero_deg() {
    int i = blockIdx.x * blockDim.x + threadIdx.x;
    if (i < NN) g_deg[i] = 0;
}

__global__ void k_hist(const int* __restrict__ ei) {
    int e = blockIdx.x * blockDim.x + threadIdx.x;
    if (e < NE) atomicAdd(&g_deg[ei[e]], 1);   // ei[0..NE) = dst
}

__global__ void k_scan1() {
    __shared__ int s[1024];
    int tid = threadIdx.x;
    int i = blockIdx.x * 1024 + tid;
    int v = (i < NN) ? g_deg[i] : 0;
    s[tid] = v;
    __syncthreads();
#pragma unroll
    for (int off = 1; off < 1024; off <<= 1) {
        int t = (tid >= off) ? s[tid - off] : 0;
        __syncthreads();
        s[tid] += t;
        __syncthreads();
    }
    if (i < NN) g_stmp[i] = s[tid];
    if (tid == 1023) g_bsum[blockIdx.x] = s[1023];
}

__global__ void k_scan2(int nb) {
    if (threadIdx.x == 0) {
        int acc = 0;
        for (int b = 0; b < nb; b++) { int t = g_bsum[b]; g_bsum[b] = acc; acc += t; }
    }
}

__global__ void k_scan3() {
    int i = blockIdx.x * blockDim.x + threadIdx.x;
    if (i < NN) {
        int incl = g_stmp[i] + g_bsum[i >> 10];
        g_rowptr[i + 1] = incl;
        g_fill[i] = incl - g_deg[i];
        if (i == 0) g_rowptr[0] = 0;
    }
}

__global__ void k_fill(const int* __restrict__ ei, const float* __restrict__ ew) {
    int e = blockIdx.x * blockDim.x + threadIdx.x;
    if (e < NE) {
        int d = ei[e];
        int s = ei[NE + e];
        int p = atomicAdd(&g_fill[d], 1);
        g_ci[p] = s;
        g_cw[p] = ew[e];
    }
}

// ---------------- TF32 MMA GEMM ----------------------------------------------
// C[m,n] = sum_k A[m,k] * W[n,k] + bias[n],  N == BN exactly.
// BM=128, BK=32, 256 threads = 8 warps in 2(m) x 4(n) grid; warp tile 64 x BN/4.
// Smem holds tiles in FRAGMENT-MAJOR layout (tf32-converted at store time) so the
// mainloop reads fragments with single LDS.128 / LDS.64 per tile.

__device__ __forceinline__ unsigned f2tf32(float x) {
    unsigned r;
    asm("cvt.rna.tf32.f32 %0, %1;" : "=r"(r) : "f"(x));
    return r;
}

__device__ __forceinline__ void mma_tf32(float* d, const uint4& a, const uint2& b) {
    asm volatile(
        "mma.sync.aligned.m16n8k8.row.col.f32.tf32.tf32.f32 "
        "{%0,%1,%2,%3}, {%4,%5,%6,%7}, {%8,%9}, {%0,%1,%2,%3};"
        : "+f"(d[0]), "+f"(d[1]), "+f"(d[2]), "+f"(d[3])
        : "r"(a.x), "r"(a.y), "r"(a.z), "r"(a.w), "r"(b.x), "r"(b.y));
}

template <int BN>
__global__ void k_mma_gemm(const float* __restrict__ A, const float* __restrict__ W,
                           const float* __restrict__ bias, float* __restrict__ C,
                           int M, int K) {
    constexpr int BM = 128, BK = 32;
    constexpr int KS = BK / 8;          // 4 k-steps per tile
    constexpr int MT_TOT = BM / 16;     // 8 m-tiles
    constexpr int NT_TOT = BN / 8;      // 16 (BN=128) or 8 (BN=64)
    constexpr int WARP_N = BN / 4;      // 32 or 16
    constexpr int NT = WARP_N / 8;      // 4 or 2
    constexpr int A_F4 = BM * BK / 4 / 256;  // 4 float4 per thread
    constexpr int B_F4 = BN * BK / 4 / 256;  // 4 or 2

    __shared__ uint4 sA[KS * MT_TOT * 32];   // 16 KB
    __shared__ uint2 sB[KS * NT_TOT * 32];   // 16 KB / 8 KB

    const int tid = threadIdx.x, lane = tid & 31, wid = tid >> 5;
    const int warp_m = wid & 1, warp_n = wid >> 1;
    const int m0 = blockIdx.x * BM;

    float acc[4][NT][4];
#pragma unroll
    for (int mt = 0; mt < 4; mt++)
#pragma unroll
        for (int nt = 0; nt < NT; nt++)
#pragma unroll
            for (int r = 0; r < 4; r++) acc[mt][nt][r] = 0.f;

    float4 pa[A_F4], pb[B_F4];

    auto loadA = [&](int k0) {
#pragma unroll
        for (int j = 0; j < A_F4; j++) {
            int f = tid + j * 256;
            int m = f >> 3, c = f & 7;
            int gm = m0 + m;
            pa[j] = (gm < M)
                ? *reinterpret_cast<const float4*>(A + (size_t)gm * K + k0 + c * 4)
                : make_float4(0.f, 0.f, 0.f, 0.f);
        }
    };
    auto loadB = [&](int k0) {
#pragma unroll
        for (int j = 0; j < B_F4; j++) {
            int f = tid + j * 256;
            int n = f >> 3, c = f & 7;
            pb[j] = *reinterpret_cast<const float4*>(W + (size_t)n * K + k0 + c * 4);
        }
    };
    auto storeTiles = [&]() {
        float* sAf = (float*)sA;
        float* sBf = (float*)sB;
#pragma unroll
        for (int j = 0; j < A_F4; j++) {
            int f = tid + j * 256;
            int m = f >> 3, c = f & 7;
            int ks = c >> 1, half = c & 1;
            int row = m & 15, mt = m >> 4;
            int reg = half * 2 + (row >> 3);
            int lbase = (ks * MT_TOT + mt) * 32 + (row & 7) * 4;
            float v[4] = {pa[j].x, pa[j].y, pa[j].z, pa[j].w};
#pragma unroll
            for (int i = 0; i < 4; i++)
                sAf[(lbase + i) * 4 + reg] = __uint_as_float(f2tf32(v[i]));
        }
#pragma unroll
        for (int j = 0; j < B_F4; j++) {
            int f = tid + j * 256;
            int n = f >> 3, c = f & 7;
            int ks = c >> 1, half = c & 1;
            int lbase = (ks * NT_TOT + (n >> 3)) * 32 + (n & 7) * 4;
            float v[4] = {pb[j].x, pb[j].y, pb[j].z, pb[j].w};
#pragma unroll
            for (int i = 0; i < 4; i++)
                sBf[(lbase + i) * 2 + half] = __uint_as_float(f2tf32(v[i]));
        }
    };

    loadA(0); loadB(0);

    for (int k0 = 0;;) {
        storeTiles();
        __syncthreads();
        k0 += BK;
        const bool more = (k0 < K);
        if (more) { loadA(k0); loadB(k0); }

#pragma unroll
        for (int ks = 0; ks < KS; ks++) {
            uint4 af[4];
#pragma unroll
            for (int mt = 0; mt < 4; mt++)
                af[mt] = sA[(ks * MT_TOT + warp_m * 4 + mt) * 32 + lane];
            uint2 bf[NT];
#pragma unroll
            for (int nt = 0; nt < NT; nt++)
                bf[nt] = sB[(ks * NT_TOT + warp_n * NT + nt) * 32 + lane];
#pragma unroll
            for (int mt = 0; mt < 4; mt++)
#pragma unroll
                for (int nt = 0; nt < NT; nt++)
                    mma_tf32(acc[mt][nt], af[mt], bf[nt]);
        }
        if (!more) break;
        __syncthreads();
    }

    // epilogue: add bias, write C (N == BN)
#pragma unroll
    for (int mt = 0; mt < 4; mt++) {
        int r0 = m0 + warp_m * 64 + mt * 16 + (lane >> 2);
#pragma unroll
        for (int nt = 0; nt < NT; nt++) {
            int col = warp_n * WARP_N + nt * 8 + (lane & 3) * 2;
            float bx = bias[col], by = bias[col + 1];
            if (r0 < M) {
                float2 v = make_float2(acc[mt][nt][0] + bx, acc[mt][nt][1] + by);
                *reinterpret_cast<float2*>(C + (size_t)r0 * BN + col) = v;
            }
            if (r0 + 8 < M) {
                float2 v = make_float2(acc[mt][nt][2] + bx, acc[mt][nt][3] + by);
                *reinterpret_cast<float2*>(C + (size_t)(r0 + 8) * BN + col) = v;
            }
        }
    }
}

// ---------------- SpMM gather: one warp per dst row ---------------------------
template <bool RELU>
__global__ void k_spmm128(const float* __restrict__ Hsrc, float* __restrict__ O) {
    int w = (blockIdx.x * blockDim.x + threadIdx.x) >> 5;
    if (w >= NN) return;
    int lane = threadIdx.x & 31;
    int beg = g_rowptr[w], end = g_rowptr[w + 1];
    float4 acc = make_float4(0.f, 0.f, 0.f, 0.f);
    for (int e = beg; e < end; e += 32) {
        int idx = e + lane;
        int s = 0; float wt = 0.f;
        if (idx < end) { s = g_ci[idx]; wt = g_cw[idx]; }
        int cnt = min(32, end - e);
        for (int j = 0; j < cnt; j++) {
            int sj = __shfl_sync(0xffffffffu, s, j);
            float wj = __shfl_sync(0xffffffffu, wt, j);
            float4 v = *reinterpret_cast<const float4*>(Hsrc + (size_t)sj * H1 + lane * 4);
            acc.x = fmaf(wj, v.x, acc.x);
            acc.y = fmaf(wj, v.y, acc.y);
            acc.z = fmaf(wj, v.z, acc.z);
            acc.w = fmaf(wj, v.w, acc.w);
        }
    }
    if (RELU) {
        acc.x = fmaxf(acc.x, 0.f); acc.y = fmaxf(acc.y, 0.f);
        acc.z = fmaxf(acc.z, 0.f); acc.w = fmaxf(acc.w, 0.f);
    }
    *reinterpret_cast<float4*>(O + (size_t)w * H1 + lane * 4) = acc;
}

__global__ void k_spmm64_norm(const float* __restrict__ Z, float* __restrict__ O) {
    int w = (blockIdx.x * blockDim.x + threadIdx.x) >> 5;
    if (w >= NN) return;
    int lane = threadIdx.x & 31;
    int beg = g_rowptr[w], end = g_rowptr[w + 1];
    float2 acc = make_float2(0.f, 0.f);
    for (int e = beg; e < end; e += 32) {
        int idx = e + lane;
        int s = 0; float wt = 0.f;
        if (idx < end) { s = g_ci[idx]; wt = g_cw[idx]; }
        int cnt = min(32, end - e);
        for (int j = 0; j < cnt; j++) {
            int sj = __shfl_sync(0xffffffffu, s, j);
            float wj = __shfl_sync(0xffffffffu, wt, j);
            float2 v = *reinterpret_cast<const float2*>(Z + (size_t)sj * H2 + lane * 2);
            acc.x = fmaf(wj, v.x, acc.x);
            acc.y = fmaf(wj, v.y, acc.y);
        }
    }
    float ss = acc.x * acc.x + acc.y * acc.y;
#pragma unroll
    for (int off = 16; off > 0; off >>= 1) ss += __shfl_xor_sync(0xffffffffu, ss, off);
    float inv = 1.f / fmaxf(sqrtf(ss), 1e-12f);
    float2 o = make_float2(acc.x * inv, acc.y * inv);
    *reinterpret_cast<float2*>(O + (size_t)w * H2 + lane * 2) = o;
}

// ---------------- launch ------------------------------------------------------
extern "C" void kernel_launch(void* const* d_in, const int* in_sizes, int n_in,
                              void* d_out, int out_size) {
    const float* x  = (const float*)d_in[0];
    const int*   ei = (const int*)d_in[1];
    const float* ew = (const float*)d_in[2];
    const float* W1 = (const float*)d_in[3];
    const float* b1 = (const float*)d_in[4];
    const float* W2 = (const float*)d_in[5];
    const float* b2 = (const float*)d_in[6];
    float* out = (float*)d_out;

    void *p_h1, *p_h2, *p_z1;
    cudaGetSymbolAddress(&p_h1, g_h1);
    cudaGetSymbolAddress(&p_h2, g_h2);
    cudaGetSymbolAddress(&p_z1, g_z1);
    float* h1 = (float*)p_h1;
    float* h2 = (float*)p_h2;
    float* z1 = (float*)p_z1;

    const int NB = (NN + 1023) / 1024;

    // CSR build (by dst)
    k_zero_deg<<<(NN + 255) / 256, 256>>>();
    k_hist<<<(NE + 255) / 256, 256>>>(ei);
    k_scan1<<<NB, 1024>>>();
    k_scan2<<<1, 32>>>(NB);
    k_scan3<<<(NN + 255) / 256, 256>>>();
    k_fill<<<(NE + 255) / 256, 256>>>(ei, ew);

    const int GRID_M = (NN + 127) / 128;  // 782

    // Layer 1: h1 = x @ W1^T + b1   (tf32 MMA)
    k_mma_gemm<128><<<GRID_M, 256>>>(x, W1, b1, h1, NN, 256);
    // h2 = relu(spmm(h1))
    k_spmm128<true><<<(NN * 32 + 255) / 256, 256>>>(h1, h2);

    // Layer 2: z1 = h2 @ W2^T + b2  (tf32 MMA)
    k_mma_gemm<64><<<GRID_M, 256>>>(h2, W2, b2, z1, NN, 128);
    // out = normalize(spmm(z1))
    k_spmm64_norm<<<(NN * 32 + 255) / 256, 256>>>(z1, out);
}